// round 16
// baseline (speedup 1.0000x reference)
#include <cuda_runtime.h>
#include <cuda_bf16.h>
#include <math.h>
#include <float.h>
#include <stdint.h>

// ---------------------------------------------------------------------------
// Problem constants
// ---------------------------------------------------------------------------
#define B_     4
#define N_     2048
#define TOK    8192
#define DIM_   768
#define NH_    12
#define HD_    64
#define HID_   3072
#define QKVD_  2304
#define EPS_   1e-6f

// ---------------------------------------------------------------------------
// mma.sync / ldmatrix helpers (sm_80+ PTX; compiles for plain compute_103)
// ---------------------------------------------------------------------------
__device__ __forceinline__ uint32_t smem_to_u32(const void* p) {
    uint32_t a;
    asm("{ .reg .u64 t; cvta.to.shared.u64 t, %1; cvt.u32.u64 %0, t; }"
        : "=r"(a) : "l"(p));
    return a;
}

#define LDMATRIX_X4(r0, r1, r2, r3, addr) \
    asm volatile("ldmatrix.sync.aligned.m8n8.x4.shared.b16 {%0,%1,%2,%3}, [%4];" \
                 : "=r"(r0), "=r"(r1), "=r"(r2), "=r"(r3) : "r"(addr))

__device__ __forceinline__ void mma_bf16(float* c, const uint32_t* a,
                                         uint32_t b0, uint32_t b1) {
    asm volatile(
        "mma.sync.aligned.m16n8k16.row.col.f32.bf16.bf16.f32 "
        "{%0,%1,%2,%3}, {%4,%5,%6,%7}, {%8,%9}, {%0,%1,%2,%3};"
        : "+f"(c[0]), "+f"(c[1]), "+f"(c[2]), "+f"(c[3])
        : "r"(a[0]), "r"(a[1]), "r"(a[2]), "r"(a[3]), "r"(b0), "r"(b1));
}

__device__ __forceinline__ void bf16_split(float x, __nv_bfloat16& h, __nv_bfloat16& l) {
    h = __float2bfloat16(x);
    l = __float2bfloat16(x - __bfloat162float(h));
}

// ---------------------------------------------------------------------------
// Scratch (__device__ globals, allocation-free)
// ---------------------------------------------------------------------------
__device__ __nv_bfloat16 g_hh [(size_t)TOK * DIM_];
__device__ __nv_bfloat16 g_hl [(size_t)TOK * DIM_];
__device__ float         g_qkv[(size_t)TOK * QKVD_];
__device__ __nv_bfloat16 g_ath[(size_t)TOK * DIM_];
__device__ __nv_bfloat16 g_atl[(size_t)TOK * DIM_];
__device__ float         g_x1 [(size_t)TOK * DIM_];
__device__ __nv_bfloat16 g_h2h[(size_t)TOK * DIM_];
__device__ __nv_bfloat16 g_h2l[(size_t)TOK * DIM_];
__device__ __nv_bfloat16 g_fh [(size_t)TOK * HID_];
__device__ __nv_bfloat16 g_fl [(size_t)TOK * HID_];
__device__ __nv_bfloat16 g_wqh[(size_t)QKVD_ * DIM_];
__device__ __nv_bfloat16 g_wql[(size_t)QKVD_ * DIM_];
__device__ __nv_bfloat16 g_wph[(size_t)DIM_ * DIM_];
__device__ __nv_bfloat16 g_wpl[(size_t)DIM_ * DIM_];
__device__ __nv_bfloat16 g_w1h[(size_t)HID_ * DIM_];
__device__ __nv_bfloat16 g_w1l[(size_t)HID_ * DIM_];
__device__ __nv_bfloat16 g_w2h[(size_t)DIM_ * HID_];
__device__ __nv_bfloat16 g_w2l[(size_t)DIM_ * HID_];

// ---------------------------------------------------------------------------
// Weight fp32 -> (hi, lo) bf16 split
// ---------------------------------------------------------------------------
__global__ __launch_bounds__(256) void split_kernel(
    const float* __restrict__ w, __nv_bfloat16* __restrict__ h,
    __nv_bfloat16* __restrict__ l, int n)
{
    for (int i = blockIdx.x * 256 + threadIdx.x; i < n; i += gridDim.x * 256) {
        __nv_bfloat16 hh, ll;
        bf16_split(w[i], hh, ll);
        h[i] = hh; l[i] = ll;
    }
}

// ---------------------------------------------------------------------------
// LayerNorm: one block per row, writes (hi, lo) bf16
// ---------------------------------------------------------------------------
__device__ __forceinline__ float warp_sum(float v) {
#pragma unroll
    for (int off = 16; off >= 1; off >>= 1)
        v += __shfl_xor_sync(0xffffffffu, v, off);
    return v;
}

__global__ __launch_bounds__(256) void ln_kernel(
    const float* __restrict__ x, const float* __restrict__ g,
    const float* __restrict__ b,
    __nv_bfloat16* __restrict__ yh, __nv_bfloat16* __restrict__ yl)
{
    const int row = blockIdx.x;
    const int tid = threadIdx.x;
    const float* xr = x + (size_t)row * DIM_;

    float v0 = xr[tid], v1 = xr[tid + 256], v2 = xr[tid + 512];
    float s  = v0 + v1 + v2;
    float s2 = v0 * v0 + v1 * v1 + v2 * v2;

    __shared__ float sm[16];
    s = warp_sum(s); s2 = warp_sum(s2);
    const int w = tid >> 5, ln = tid & 31;
    if (ln == 0) { sm[w] = s; sm[8 + w] = s2; }
    __syncthreads();
    float ts = 0.f, ts2 = 0.f;
#pragma unroll
    for (int i = 0; i < 8; i++) { ts += sm[i]; ts2 += sm[8 + i]; }

    const float mu  = ts * (1.f / DIM_);
    const float var = ts2 * (1.f / DIM_) - mu * mu;
    const float inv = rsqrtf(var + EPS_);

    const size_t base = (size_t)row * DIM_;
#pragma unroll
    for (int c = 0; c < 3; c++) {
        const int col = tid + 256 * c;
        const float v = (c == 0 ? v0 : (c == 1 ? v1 : v2));
        const float y = (v - mu) * inv * g[col] + b[col];
        __nv_bfloat16 hh, ll;
        bf16_split(y, hh, ll);
        yh[base + col] = hh; yl[base + col] = ll;
    }
}

// ---------------------------------------------------------------------------
// HMMA split-precision NT GEMM:
//   C[M,N] = (Ah+Al)[M,K] @ (Bh+Bl)[N,K]^T   (AhBh + AlBh + AhBl)
// 128x128 tile, BK=32 bf16, 256 threads.
// 8 warps in 2(M) x 4(N); warp tile 64x32 = 4x4 mma.m16n8k16 tiles.
// smem rows padded to 40 bf16 (stride 80B, gcd(5,8)=1 -> conflict-free ldmatrix).
// EPI: 0 = bias->f32 ; 1 = bias+res->f32 ; 2 = bias+GELU->(hi,lo) bf16
// ---------------------------------------------------------------------------
#define GST 40   // smem row stride in bf16

template<int EPI>
__global__ __launch_bounds__(256) void gemm_mma(
    const __nv_bfloat16* __restrict__ Ah, const __nv_bfloat16* __restrict__ Al,
    const __nv_bfloat16* __restrict__ Bh, const __nv_bfloat16* __restrict__ Bl,
    const float* __restrict__ bias, const float* __restrict__ res,
    float* __restrict__ Cf,
    __nv_bfloat16* __restrict__ Ch, __nv_bfloat16* __restrict__ Cl,
    int N, int K)
{
    __shared__ __nv_bfloat16 sAh[128 * GST];
    __shared__ __nv_bfloat16 sAl[128 * GST];
    __shared__ __nv_bfloat16 sBh[128 * GST];
    __shared__ __nv_bfloat16 sBl[128 * GST];

    const int tid  = threadIdx.x;
    const int wid  = tid >> 5;
    const int lane = tid & 31;
    const int wm = wid & 1;          // 2 warps along M (64 rows each)
    const int wn = wid >> 1;         // 4 warps along N (32 cols each)
    const int g  = lane >> 2;        // mma group row
    const int t4 = lane & 3;         // mma quad col
    const int bm = blockIdx.y * 128;
    const int bn = blockIdx.x * 128;

    // --- loader mapping: 2 positions per thread per array ---
    const int row0 = tid >> 2;             // 0..63
    const int cc0  = (tid & 3) * 8;        // 0,8,16,24
    const int row1 = row0 + 64;
    const size_t offA0 = (size_t)(bm + row0) * K + cc0;
    const size_t offA1 = (size_t)(bm + row1) * K + cc0;
    const size_t offB0 = (size_t)(bn + row0) * K + cc0;
    const size_t offB1 = (size_t)(bn + row1) * K + cc0;
    const int s0 = row0 * GST + cc0;
    const int s1 = row1 * GST + cc0;

    // --- ldmatrix lane addressing ---
    const uint32_t aAh = smem_to_u32(sAh);
    const uint32_t aAl = smem_to_u32(sAl);
    const uint32_t aBh = smem_to_u32(sBh);
    const uint32_t aBl = smem_to_u32(sBl);
    // A: lanes 0-7 rows 0-7 @k0; 8-15 rows 8-15 @k0; 16-23 rows 0-7 @k8; 24-31 rows 8-15 @k8
    const uint32_t aoff = (uint32_t)(((wm * 64 + (lane & 15)) * GST + (lane >> 4) * 8) * 2);
    // B: rows are n, cols are k
    const uint32_t brow = (lane & 7) + ((lane & 16) ? 8 : 0);
    const uint32_t bcol = (lane & 8) ? 8 : 0;
    const uint32_t boff = (uint32_t)(((wn * 32 + brow) * GST + bcol) * 2);

    float acc[4][4][4];
#pragma unroll
    for (int i = 0; i < 4; i++)
#pragma unroll
        for (int j = 0; j < 4; j++)
#pragma unroll
            for (int q = 0; q < 4; q++) acc[i][j][q] = 0.f;

    // prefetch chunk 0
    uint4 vAh0 = *(const uint4*)(Ah + offA0), vAh1 = *(const uint4*)(Ah + offA1);
    uint4 vAl0 = *(const uint4*)(Al + offA0), vAl1 = *(const uint4*)(Al + offA1);
    uint4 vBh0 = *(const uint4*)(Bh + offB0), vBh1 = *(const uint4*)(Bh + offB1);
    uint4 vBl0 = *(const uint4*)(Bl + offB0), vBl1 = *(const uint4*)(Bl + offB1);

    for (int kc = 0; kc < K; kc += 32) {
        if (kc) __syncthreads();
        *(uint4*)&sAh[s0] = vAh0; *(uint4*)&sAh[s1] = vAh1;
        *(uint4*)&sAl[s0] = vAl0; *(uint4*)&sAl[s1] = vAl1;
        *(uint4*)&sBh[s0] = vBh0; *(uint4*)&sBh[s1] = vBh1;
        *(uint4*)&sBl[s0] = vBl0; *(uint4*)&sBl[s1] = vBl1;
        __syncthreads();

        if (kc + 32 < K) {
            const int kn = kc + 32;
            vAh0 = *(const uint4*)(Ah + offA0 + kn); vAh1 = *(const uint4*)(Ah + offA1 + kn);
            vAl0 = *(const uint4*)(Al + offA0 + kn); vAl1 = *(const uint4*)(Al + offA1 + kn);
            vBh0 = *(const uint4*)(Bh + offB0 + kn); vBh1 = *(const uint4*)(Bh + offB1 + kn);
            vBl0 = *(const uint4*)(Bl + offB0 + kn); vBl1 = *(const uint4*)(Bl + offB1 + kn);
        }

#pragma unroll
        for (int ks = 0; ks < 2; ks++) {           // two K=16 steps per chunk
            const uint32_t ko = ks * 32;           // 16 bf16 = 32 bytes
            uint32_t ah[4][4], al[4][4], bh[2][4], bl[2][4];
#pragma unroll
            for (int mt = 0; mt < 4; mt++) {
                const uint32_t mo = (uint32_t)(mt * 16 * GST * 2) + ko;
                LDMATRIX_X4(ah[mt][0], ah[mt][1], ah[mt][2], ah[mt][3], aAh + aoff + mo);
                LDMATRIX_X4(al[mt][0], al[mt][1], al[mt][2], al[mt][3], aAl + aoff + mo);
            }
#pragma unroll
            for (int nb = 0; nb < 2; nb++) {
                const uint32_t no = (uint32_t)(nb * 16 * GST * 2) + ko;
                LDMATRIX_X4(bh[nb][0], bh[nb][1], bh[nb][2], bh[nb][3], aBh + boff + no);
                LDMATRIX_X4(bl[nb][0], bl[nb][1], bl[nb][2], bl[nb][3], aBl + boff + no);
            }
#pragma unroll
            for (int mt = 0; mt < 4; mt++)
#pragma unroll
                for (int nt = 0; nt < 4; nt++) {
                    const int nb = nt >> 1, pp = (nt & 1) * 2;
                    mma_bf16(acc[mt][nt], ah[mt], bh[nb][pp], bh[nb][pp + 1]);
                    mma_bf16(acc[mt][nt], al[mt], bh[nb][pp], bh[nb][pp + 1]);
                    mma_bf16(acc[mt][nt], ah[mt], bl[nb][pp], bl[nb][pp + 1]);
                }
        }
    }

    // ---- epilogue: c0,c1 = C[g][2t..], c2,c3 = C[g+8][2t..] ----
#pragma unroll
    for (int mt = 0; mt < 4; mt++)
#pragma unroll
        for (int nt = 0; nt < 4; nt++) {
            const int rm = bm + wm * 64 + mt * 16 + g;
            const int cn = bn + wn * 32 + nt * 8 + 2 * t4;
            const float b0 = bias[cn], b1 = bias[cn + 1];
#pragma unroll
            for (int hh = 0; hh < 2; hh++) {
                const int row = rm + 8 * hh;
                const size_t idx = (size_t)row * N + cn;
                float v0 = acc[mt][nt][2 * hh + 0] + b0;
                float v1 = acc[mt][nt][2 * hh + 1] + b1;
                if (EPI == 2) {
                    v0 = v0 * normcdff(v0);         // exact GELU
                    v1 = v1 * normcdff(v1);
                    __nv_bfloat16 h0, l0, h1, l1;
                    bf16_split(v0, h0, l0); bf16_split(v1, h1, l1);
                    Ch[idx] = h0; Ch[idx + 1] = h1;
                    Cl[idx] = l0; Cl[idx + 1] = l1;
                } else if (EPI == 1) {
                    Cf[idx]     = v0 + res[idx];
                    Cf[idx + 1] = v1 + res[idx + 1];
                } else {
                    Cf[idx]     = v0;
                    Cf[idx + 1] = v1;
                }
            }
        }
}

// ---------------------------------------------------------------------------
// Flash attention (fp32; output split to (hi, lo) bf16)
// ---------------------------------------------------------------------------
#define ATTN_PAD   68
#define ATTN_SMEM  (4 * 64 * ATTN_PAD * (int)sizeof(float))

__global__ __launch_bounds__(256) void attn_kernel(
    const float* __restrict__ qkv,
    __nv_bfloat16* __restrict__ outh, __nv_bfloat16* __restrict__ outl)
{
    extern __shared__ float fsm[];
    float* Qs = fsm;
    float* Ks = Qs + 64 * ATTN_PAD;
    float* Vs = Ks + 64 * ATTN_PAD;
    float* Ps = Vs + 64 * ATTN_PAD;

    const int tid = threadIdx.x;
    const int ty = tid >> 4, tx = tid & 15;
    const int bh = blockIdx.y;
    const int b  = bh / NH_;
    const int hd = bh % NH_;
    const int q0 = blockIdx.x * 64;
    const size_t rowbase = (size_t)b * N_;

    const int lr  = tid >> 2;
    const int lcl = (tid & 3) * 16;

    {
        const float* src = qkv + (rowbase + q0 + lr) * QKVD_ + hd * HD_ + lcl;
        float* dst = &Qs[lr * ATTN_PAD + lcl];
#pragma unroll
        for (int c = 0; c < 4; c++) {
            float4 t = *(const float4*)(src + 4 * c);
            t.x *= 0.125f; t.y *= 0.125f; t.z *= 0.125f; t.w *= 0.125f;
            *(float4*)(dst + 4 * c) = t;
        }
    }

    float m[4], lsum[4], o[4][4];
#pragma unroll
    for (int i = 0; i < 4; i++) {
        m[i] = -FLT_MAX; lsum[i] = 0.f;
#pragma unroll
        for (int j = 0; j < 4; j++) o[i][j] = 0.f;
    }

    float4 kreg[4], vreg[4];
    {
        const float* ksrc = qkv + (rowbase + lr) * QKVD_ + DIM_ + hd * HD_ + lcl;
        const float* vsrc = qkv + (rowbase + lr) * QKVD_ + 2 * DIM_ + hd * HD_ + lcl;
#pragma unroll
        for (int c = 0; c < 4; c++) {
            kreg[c] = *(const float4*)(ksrc + 4 * c);
            vreg[c] = *(const float4*)(vsrc + 4 * c);
        }
    }

    for (int t = 0; t < N_ / 64; t++) {
        __syncthreads();
        {
            float* kd = &Ks[lr * ATTN_PAD + lcl];
            float* vd = &Vs[lr * ATTN_PAD + lcl];
#pragma unroll
            for (int c = 0; c < 4; c++) {
                *(float4*)(kd + 4 * c) = kreg[c];
                *(float4*)(vd + 4 * c) = vreg[c];
            }
        }
        __syncthreads();
        if (t + 1 < N_ / 64) {
            const size_t r = rowbase + (size_t)(t + 1) * 64 + lr;
            const float* ksrc = qkv + r * QKVD_ + DIM_ + hd * HD_ + lcl;
            const float* vsrc = qkv + r * QKVD_ + 2 * DIM_ + hd * HD_ + lcl;
#pragma unroll
            for (int c = 0; c < 4; c++) {
                kreg[c] = *(const float4*)(ksrc + 4 * c);
                vreg[c] = *(const float4*)(vsrc + 4 * c);
            }
        }

        float s[4][4];
#pragma unroll
        for (int i = 0; i < 4; i++)
#pragma unroll
            for (int j = 0; j < 4; j++) s[i][j] = 0.f;

#pragma unroll
        for (int d4 = 0; d4 < 16; d4++) {
            float4 qa[4], kb[4];
#pragma unroll
            for (int i = 0; i < 4; i++)
                qa[i] = *(const float4*)&Qs[(ty + 16 * i) * ATTN_PAD + 4 * d4];
#pragma unroll
            for (int j = 0; j < 4; j++)
                kb[j] = *(const float4*)&Ks[(tx + 16 * j) * ATTN_PAD + 4 * d4];
#pragma unroll
            for (int i = 0; i < 4; i++)
#pragma unroll
                for (int j = 0; j < 4; j++)
                    s[i][j] += qa[i].x * kb[j].x + qa[i].y * kb[j].y
                             + qa[i].z * kb[j].z + qa[i].w * kb[j].w;
        }

#pragma unroll
        for (int i = 0; i < 4; i++) {
            float mx = fmaxf(fmaxf(s[i][0], s[i][1]), fmaxf(s[i][2], s[i][3]));
#pragma unroll
            for (int off = 8; off >= 1; off >>= 1)
                mx = fmaxf(mx, __shfl_xor_sync(0xffffffffu, mx, off));
            const float mn = fmaxf(m[i], mx);
            const float p0 = __expf(s[i][0] - mn);
            const float p1 = __expf(s[i][1] - mn);
            const float p2 = __expf(s[i][2] - mn);
            const float p3 = __expf(s[i][3] - mn);
            float ls = p0 + p1 + p2 + p3;
#pragma unroll
            for (int off = 8; off >= 1; off >>= 1)
                ls += __shfl_xor_sync(0xffffffffu, ls, off);
            const float alpha = __expf(m[i] - mn);
            m[i] = mn;
            lsum[i] = lsum[i] * alpha + ls;
            o[i][0] *= alpha; o[i][1] *= alpha; o[i][2] *= alpha; o[i][3] *= alpha;
            float* pr = &Ps[(ty + 16 * i) * ATTN_PAD + tx];
            pr[0] = p0; pr[16] = p1; pr[32] = p2; pr[48] = p3;
        }
        __syncthreads();

#pragma unroll
        for (int k4 = 0; k4 < 16; k4++) {
            float pr[4][4];
#pragma unroll
            for (int i = 0; i < 4; i++) {
                float4 tt = *(const float4*)&Ps[(ty + 16 * i) * ATTN_PAD + 4 * k4];
                pr[i][0] = tt.x; pr[i][1] = tt.y; pr[i][2] = tt.z; pr[i][3] = tt.w;
            }
#pragma unroll
            for (int kk = 0; kk < 4; kk++) {
                float vb[4];
#pragma unroll
                for (int j = 0; j < 4; j++)
                    vb[j] = Vs[(4 * k4 + kk) * ATTN_PAD + tx + 16 * j];
#pragma unroll
                for (int i = 0; i < 4; i++)
#pragma unroll
                    for (int j = 0; j < 4; j++)
                        o[i][j] += pr[i][kk] * vb[j];
            }
        }
    }

#pragma unroll
    for (int i = 0; i < 4; i++) {
        const float invl = 1.f / lsum[i];
        const size_t base = (rowbase + q0 + ty + 16 * i) * DIM_ + hd * HD_ + tx;
#pragma unroll
        for (int j = 0; j < 4; j++) {
            const float v = o[i][j] * invl;
            __nv_bfloat16 hh, ll;
            bf16_split(v, hh, ll);
            outh[base + 16 * j] = hh;
            outl[base + 16 * j] = ll;
        }
    }
}

// ---------------------------------------------------------------------------
// Launch
// ---------------------------------------------------------------------------
extern "C" void kernel_launch(void* const* d_in, const int* in_sizes, int n_in,
                              void* d_out, int out_size)
{
    const float* x      = (const float*)d_in[0];
    const float* ln1_g  = (const float*)d_in[1];
    const float* ln1_b  = (const float*)d_in[2];
    const float* qkv_w  = (const float*)d_in[3];
    const float* qkv_b  = (const float*)d_in[4];
    const float* proj_w = (const float*)d_in[5];
    const float* proj_b = (const float*)d_in[6];
    const float* ln2_g  = (const float*)d_in[7];
    const float* ln2_b  = (const float*)d_in[8];
    const float* fc1_w  = (const float*)d_in[9];
    const float* fc1_b  = (const float*)d_in[10];
    const float* fc2_w  = (const float*)d_in[11];
    const float* fc2_b  = (const float*)d_in[12];
    float* out = (float*)d_out;

    __nv_bfloat16 *phh, *phl, *path, *patl, *ph2h, *ph2l, *pfh, *pfl;
    __nv_bfloat16 *pwqh, *pwql, *pwph, *pwpl, *pw1h, *pw1l, *pw2h, *pw2l;
    float *pqkv, *px1;
    cudaGetSymbolAddress((void**)&phh,  g_hh);
    cudaGetSymbolAddress((void**)&phl,  g_hl);
    cudaGetSymbolAddress((void**)&pqkv, g_qkv);
    cudaGetSymbolAddress((void**)&path, g_ath);
    cudaGetSymbolAddress((void**)&patl, g_atl);
    cudaGetSymbolAddress((void**)&px1,  g_x1);
    cudaGetSymbolAddress((void**)&ph2h, g_h2h);
    cudaGetSymbolAddress((void**)&ph2l, g_h2l);
    cudaGetSymbolAddress((void**)&pfh,  g_fh);
    cudaGetSymbolAddress((void**)&pfl,  g_fl);
    cudaGetSymbolAddress((void**)&pwqh, g_wqh);
    cudaGetSymbolAddress((void**)&pwql, g_wql);
    cudaGetSymbolAddress((void**)&pwph, g_wph);
    cudaGetSymbolAddress((void**)&pwpl, g_wpl);
    cudaGetSymbolAddress((void**)&pw1h, g_w1h);
    cudaGetSymbolAddress((void**)&pw1l, g_w1l);
    cudaGetSymbolAddress((void**)&pw2h, g_w2h);
    cudaGetSymbolAddress((void**)&pw2l, g_w2l);

    cudaFuncSetAttribute(attn_kernel,
                         cudaFuncAttributeMaxDynamicSharedMemorySize, ATTN_SMEM);

    // 0. split weights to (hi, lo) bf16
    split_kernel<<<256, 256>>>(qkv_w,  pwqh, pwql, QKVD_ * DIM_);
    split_kernel<<<256, 256>>>(proj_w, pwph, pwpl, DIM_ * DIM_);
    split_kernel<<<256, 256>>>(fc1_w,  pw1h, pw1l, HID_ * DIM_);
    split_kernel<<<256, 256>>>(fc2_w,  pw2h, pw2l, DIM_ * HID_);

    // 1. h = LN1(x)  -> bf16 split
    ln_kernel<<<TOK, 256>>>(x, ln1_g, ln1_b, phh, phl);
    // 2. qkv = h @ Wqkv^T + b   (fp32 out)
    gemm_mma<0><<<dim3(QKVD_ / 128, TOK / 128), 256>>>(
        phh, phl, pwqh, pwql, qkv_b, nullptr, pqkv, nullptr, nullptr, QKVD_, DIM_);
    // 3. attention -> bf16 split
    attn_kernel<<<dim3(N_ / 64, B_ * NH_), 256, ATTN_SMEM>>>(pqkv, path, patl);
    // 4. x1 = x + attn @ Wproj^T + b
    gemm_mma<1><<<dim3(DIM_ / 128, TOK / 128), 256>>>(
        path, patl, pwph, pwpl, proj_b, x, px1, nullptr, nullptr, DIM_, DIM_);
    // 5. h2 = LN2(x1) -> bf16 split
    ln_kernel<<<TOK, 256>>>(px1, ln2_g, ln2_b, ph2h, ph2l);
    // 6. ffn = gelu(h2 @ Wfc1^T + b) -> bf16 split
    gemm_mma<2><<<dim3(HID_ / 128, TOK / 128), 256>>>(
        ph2h, ph2l, pw1h, pw1l, fc1_b, nullptr, nullptr, pfh, pfl, HID_, DIM_);
    // 7. out = x1 + ffn @ Wfc2^T + b
    gemm_mma<1><<<dim3(DIM_ / 128, TOK / 128), 256>>>(
        pfh, pfl, pw2h, pw2l, fc2_b, px1, out, nullptr, nullptr, DIM_, HID_);
}

// round 17
// speedup vs baseline: 1.0004x; 1.0004x over previous
#include <cuda_runtime.h>
#include <cuda_bf16.h>
#include <math.h>
#include <float.h>
#include <stdint.h>

// ---------------------------------------------------------------------------
// Problem constants
// ---------------------------------------------------------------------------
#define B_     4
#define N_     2048
#define TOK    8192
#define DIM_   768
#define NH_    12
#define HD_    64
#define HID_   3072
#define QKVD_  2304
#define EPS_   1e-6f

// ---------------------------------------------------------------------------
// mma.sync / ldmatrix helpers (sm_80+ PTX; compiles for plain compute_103)
// ---------------------------------------------------------------------------
__device__ __forceinline__ uint32_t smem_to_u32(const void* p) {
    uint32_t a;
    asm("{ .reg .u64 t; cvta.to.shared.u64 t, %1; cvt.u32.u64 %0, t; }"
        : "=r"(a) : "l"(p));
    return a;
}

#define LDMATRIX_X4(r0, r1, r2, r3, addr) \
    asm volatile("ldmatrix.sync.aligned.m8n8.x4.shared.b16 {%0,%1,%2,%3}, [%4];" \
                 : "=r"(r0), "=r"(r1), "=r"(r2), "=r"(r3) : "r"(addr))

__device__ __forceinline__ void mma_bf16(float* c, const uint32_t* a,
                                         uint32_t b0, uint32_t b1) {
    asm volatile(
        "mma.sync.aligned.m16n8k16.row.col.f32.bf16.bf16.f32 "
        "{%0,%1,%2,%3}, {%4,%5,%6,%7}, {%8,%9}, {%0,%1,%2,%3};"
        : "+f"(c[0]), "+f"(c[1]), "+f"(c[2]), "+f"(c[3])
        : "r"(a[0]), "r"(a[1]), "r"(a[2]), "r"(a[3]), "r"(b0), "r"(b1));
}

__device__ __forceinline__ void bf16_split(float x, __nv_bfloat16& h, __nv_bfloat16& l) {
    h = __float2bfloat16(x);
    l = __float2bfloat16(x - __bfloat162float(h));
}

// ---------------------------------------------------------------------------
// Scratch (__device__ globals, allocation-free)
// ---------------------------------------------------------------------------
__device__ __nv_bfloat16 g_hh [(size_t)TOK * DIM_];
__device__ __nv_bfloat16 g_hl [(size_t)TOK * DIM_];
__device__ float         g_qkv[(size_t)TOK * QKVD_];
__device__ __nv_bfloat16 g_ath[(size_t)TOK * DIM_];
__device__ __nv_bfloat16 g_atl[(size_t)TOK * DIM_];
__device__ float         g_x1 [(size_t)TOK * DIM_];
__device__ __nv_bfloat16 g_h2h[(size_t)TOK * DIM_];
__device__ __nv_bfloat16 g_h2l[(size_t)TOK * DIM_];
__device__ __nv_bfloat16 g_fh [(size_t)TOK * HID_];
__device__ __nv_bfloat16 g_fl [(size_t)TOK * HID_];
__device__ __nv_bfloat16 g_wqh[(size_t)QKVD_ * DIM_];
__device__ __nv_bfloat16 g_wql[(size_t)QKVD_ * DIM_];
__device__ __nv_bfloat16 g_wph[(size_t)DIM_ * DIM_];
__device__ __nv_bfloat16 g_wpl[(size_t)DIM_ * DIM_];
__device__ __nv_bfloat16 g_w1h[(size_t)HID_ * DIM_];
__device__ __nv_bfloat16 g_w1l[(size_t)HID_ * DIM_];
__device__ __nv_bfloat16 g_w2h[(size_t)DIM_ * HID_];
__device__ __nv_bfloat16 g_w2l[(size_t)DIM_ * HID_];

// ---------------------------------------------------------------------------
// Weight fp32 -> (hi, lo) bf16 split
// ---------------------------------------------------------------------------
__global__ __launch_bounds__(256) void split_kernel(
    const float* __restrict__ w, __nv_bfloat16* __restrict__ h,
    __nv_bfloat16* __restrict__ l, int n)
{
    for (int i = blockIdx.x * 256 + threadIdx.x; i < n; i += gridDim.x * 256) {
        __nv_bfloat16 hh, ll;
        bf16_split(w[i], hh, ll);
        h[i] = hh; l[i] = ll;
    }
}

// ---------------------------------------------------------------------------
// LayerNorm: one block per row, writes (hi, lo) bf16
// ---------------------------------------------------------------------------
__device__ __forceinline__ float warp_sum(float v) {
#pragma unroll
    for (int off = 16; off >= 1; off >>= 1)
        v += __shfl_xor_sync(0xffffffffu, v, off);
    return v;
}

__global__ __launch_bounds__(256) void ln_kernel(
    const float* __restrict__ x, const float* __restrict__ g,
    const float* __restrict__ b,
    __nv_bfloat16* __restrict__ yh, __nv_bfloat16* __restrict__ yl)
{
    const int row = blockIdx.x;
    const int tid = threadIdx.x;
    const float* xr = x + (size_t)row * DIM_;

    float v0 = xr[tid], v1 = xr[tid + 256], v2 = xr[tid + 512];
    float s  = v0 + v1 + v2;
    float s2 = v0 * v0 + v1 * v1 + v2 * v2;

    __shared__ float sm[16];
    s = warp_sum(s); s2 = warp_sum(s2);
    const int w = tid >> 5, ln = tid & 31;
    if (ln == 0) { sm[w] = s; sm[8 + w] = s2; }
    __syncthreads();
    float ts = 0.f, ts2 = 0.f;
#pragma unroll
    for (int i = 0; i < 8; i++) { ts += sm[i]; ts2 += sm[8 + i]; }

    const float mu  = ts * (1.f / DIM_);
    const float var = ts2 * (1.f / DIM_) - mu * mu;
    const float inv = rsqrtf(var + EPS_);

    const size_t base = (size_t)row * DIM_;
#pragma unroll
    for (int c = 0; c < 3; c++) {
        const int col = tid + 256 * c;
        const float v = (c == 0 ? v0 : (c == 1 ? v1 : v2));
        const float y = (v - mu) * inv * g[col] + b[col];
        __nv_bfloat16 hh, ll;
        bf16_split(y, hh, ll);
        yh[base + col] = hh; yl[base + col] = ll;
    }
}

// ---------------------------------------------------------------------------
// HMMA split-precision NT GEMM:
//   C[M,N] = (Ah+Al)[M,K] @ (Bh+Bl)[N,K]^T   (AhBh + AlBh + AhBl)
// 128x128 tile, BK=32 bf16, 256 threads.
// 8 warps in 2(M) x 4(N); warp tile 64x32 = 4x4 mma.m16n8k16 tiles.
// smem rows padded to 40 bf16 (stride 80B, gcd(5,8)=1 -> conflict-free ldmatrix).
// EPI: 0 = bias->f32 ; 1 = bias+res->f32 ; 2 = bias+GELU->(hi,lo) bf16
// ---------------------------------------------------------------------------
#define GST 40   // smem row stride in bf16

template<int EPI>
__global__ __launch_bounds__(256) void gemm_mma(
    const __nv_bfloat16* __restrict__ Ah, const __nv_bfloat16* __restrict__ Al,
    const __nv_bfloat16* __restrict__ Bh, const __nv_bfloat16* __restrict__ Bl,
    const float* __restrict__ bias, const float* __restrict__ res,
    float* __restrict__ Cf,
    __nv_bfloat16* __restrict__ Ch, __nv_bfloat16* __restrict__ Cl,
    int N, int K)
{
    __shared__ __nv_bfloat16 sAh[128 * GST];
    __shared__ __nv_bfloat16 sAl[128 * GST];
    __shared__ __nv_bfloat16 sBh[128 * GST];
    __shared__ __nv_bfloat16 sBl[128 * GST];

    const int tid  = threadIdx.x;
    const int wid  = tid >> 5;
    const int lane = tid & 31;
    const int wm = wid & 1;          // 2 warps along M (64 rows each)
    const int wn = wid >> 1;         // 4 warps along N (32 cols each)
    const int g  = lane >> 2;        // mma group row
    const int t4 = lane & 3;         // mma quad col
    const int bm = blockIdx.y * 128;
    const int bn = blockIdx.x * 128;

    // --- loader mapping: 2 positions per thread per array ---
    const int row0 = tid >> 2;             // 0..63
    const int cc0  = (tid & 3) * 8;        // 0,8,16,24
    const int row1 = row0 + 64;
    const size_t offA0 = (size_t)(bm + row0) * K + cc0;
    const size_t offA1 = (size_t)(bm + row1) * K + cc0;
    const size_t offB0 = (size_t)(bn + row0) * K + cc0;
    const size_t offB1 = (size_t)(bn + row1) * K + cc0;
    const int s0 = row0 * GST + cc0;
    const int s1 = row1 * GST + cc0;

    // --- ldmatrix lane addressing ---
    const uint32_t aAh = smem_to_u32(sAh);
    const uint32_t aAl = smem_to_u32(sAl);
    const uint32_t aBh = smem_to_u32(sBh);
    const uint32_t aBl = smem_to_u32(sBl);
    // A: lanes 0-7 rows 0-7 @k0; 8-15 rows 8-15 @k0; 16-23 rows 0-7 @k8; 24-31 rows 8-15 @k8
    const uint32_t aoff = (uint32_t)(((wm * 64 + (lane & 15)) * GST + (lane >> 4) * 8) * 2);
    // B: rows are n, cols are k
    const uint32_t brow = (lane & 7) + ((lane & 16) ? 8 : 0);
    const uint32_t bcol = (lane & 8) ? 8 : 0;
    const uint32_t boff = (uint32_t)(((wn * 32 + brow) * GST + bcol) * 2);

    float acc[4][4][4];
#pragma unroll
    for (int i = 0; i < 4; i++)
#pragma unroll
        for (int j = 0; j < 4; j++)
#pragma unroll
            for (int q = 0; q < 4; q++) acc[i][j][q] = 0.f;

    // prefetch chunk 0
    uint4 vAh0 = *(const uint4*)(Ah + offA0), vAh1 = *(const uint4*)(Ah + offA1);
    uint4 vAl0 = *(const uint4*)(Al + offA0), vAl1 = *(const uint4*)(Al + offA1);
    uint4 vBh0 = *(const uint4*)(Bh + offB0), vBh1 = *(const uint4*)(Bh + offB1);
    uint4 vBl0 = *(const uint4*)(Bl + offB0), vBl1 = *(const uint4*)(Bl + offB1);

    for (int kc = 0; kc < K; kc += 32) {
        if (kc) __syncthreads();
        *(uint4*)&sAh[s0] = vAh0; *(uint4*)&sAh[s1] = vAh1;
        *(uint4*)&sAl[s0] = vAl0; *(uint4*)&sAl[s1] = vAl1;
        *(uint4*)&sBh[s0] = vBh0; *(uint4*)&sBh[s1] = vBh1;
        *(uint4*)&sBl[s0] = vBl0; *(uint4*)&sBl[s1] = vBl1;
        __syncthreads();

        if (kc + 32 < K) {
            const int kn = kc + 32;
            vAh0 = *(const uint4*)(Ah + offA0 + kn); vAh1 = *(const uint4*)(Ah + offA1 + kn);
            vAl0 = *(const uint4*)(Al + offA0 + kn); vAl1 = *(const uint4*)(Al + offA1 + kn);
            vBh0 = *(const uint4*)(Bh + offB0 + kn); vBh1 = *(const uint4*)(Bh + offB1 + kn);
            vBl0 = *(const uint4*)(Bl + offB0 + kn); vBl1 = *(const uint4*)(Bl + offB1 + kn);
        }

#pragma unroll
        for (int ks = 0; ks < 2; ks++) {           // two K=16 steps per chunk
            const uint32_t ko = ks * 32;           // 16 bf16 = 32 bytes
            uint32_t ah[4][4], al[4][4], bh[2][4], bl[2][4];
#pragma unroll
            for (int mt = 0; mt < 4; mt++) {
                const uint32_t mo = (uint32_t)(mt * 16 * GST * 2) + ko;
                LDMATRIX_X4(ah[mt][0], ah[mt][1], ah[mt][2], ah[mt][3], aAh + aoff + mo);
                LDMATRIX_X4(al[mt][0], al[mt][1], al[mt][2], al[mt][3], aAl + aoff + mo);
            }
#pragma unroll
            for (int nb = 0; nb < 2; nb++) {
                const uint32_t no = (uint32_t)(nb * 16 * GST * 2) + ko;
                LDMATRIX_X4(bh[nb][0], bh[nb][1], bh[nb][2], bh[nb][3], aBh + boff + no);
                LDMATRIX_X4(bl[nb][0], bl[nb][1], bl[nb][2], bl[nb][3], aBl + boff + no);
            }
#pragma unroll
            for (int mt = 0; mt < 4; mt++)
#pragma unroll
                for (int nt = 0; nt < 4; nt++) {
                    const int nb = nt >> 1, pp = (nt & 1) * 2;
                    mma_bf16(acc[mt][nt], ah[mt], bh[nb][pp], bh[nb][pp + 1]);
                    mma_bf16(acc[mt][nt], al[mt], bh[nb][pp], bh[nb][pp + 1]);
                    mma_bf16(acc[mt][nt], ah[mt], bl[nb][pp], bl[nb][pp + 1]);
                }
        }
    }

    // ---- epilogue: c0,c1 = C[g][2t..], c2,c3 = C[g+8][2t..] ----
#pragma unroll
    for (int mt = 0; mt < 4; mt++)
#pragma unroll
        for (int nt = 0; nt < 4; nt++) {
            const int rm = bm + wm * 64 + mt * 16 + g;
            const int cn = bn + wn * 32 + nt * 8 + 2 * t4;
            const float b0 = bias[cn], b1 = bias[cn + 1];
#pragma unroll
            for (int hh = 0; hh < 2; hh++) {
                const int row = rm + 8 * hh;
                const size_t idx = (size_t)row * N + cn;
                float v0 = acc[mt][nt][2 * hh + 0] + b0;
                float v1 = acc[mt][nt][2 * hh + 1] + b1;
                if (EPI == 2) {
                    v0 = v0 * normcdff(v0);         // exact GELU
                    v1 = v1 * normcdff(v1);
                    __nv_bfloat16 h0, l0, h1, l1;
                    bf16_split(v0, h0, l0); bf16_split(v1, h1, l1);
                    Ch[idx] = h0; Ch[idx + 1] = h1;
                    Cl[idx] = l0; Cl[idx + 1] = l1;
                } else if (EPI == 1) {
                    Cf[idx]     = v0 + res[idx];
                    Cf[idx + 1] = v1 + res[idx + 1];
                } else {
                    Cf[idx]     = v0;
                    Cf[idx + 1] = v1;
                }
            }
        }
}

// ---------------------------------------------------------------------------
// Flash attention (fp32; output split to (hi, lo) bf16)
// ---------------------------------------------------------------------------
#define ATTN_PAD   68
#define ATTN_SMEM  (4 * 64 * ATTN_PAD * (int)sizeof(float))

__global__ __launch_bounds__(256) void attn_kernel(
    const float* __restrict__ qkv,
    __nv_bfloat16* __restrict__ outh, __nv_bfloat16* __restrict__ outl)
{
    extern __shared__ float fsm[];
    float* Qs = fsm;
    float* Ks = Qs + 64 * ATTN_PAD;
    float* Vs = Ks + 64 * ATTN_PAD;
    float* Ps = Vs + 64 * ATTN_PAD;

    const int tid = threadIdx.x;
    const int ty = tid >> 4, tx = tid & 15;
    const int bh = blockIdx.y;
    const int b  = bh / NH_;
    const int hd = bh % NH_;
    const int q0 = blockIdx.x * 64;
    const size_t rowbase = (size_t)b * N_;

    const int lr  = tid >> 2;
    const int lcl = (tid & 3) * 16;

    {
        const float* src = qkv + (rowbase + q0 + lr) * QKVD_ + hd * HD_ + lcl;
        float* dst = &Qs[lr * ATTN_PAD + lcl];
#pragma unroll
        for (int c = 0; c < 4; c++) {
            float4 t = *(const float4*)(src + 4 * c);
            t.x *= 0.125f; t.y *= 0.125f; t.z *= 0.125f; t.w *= 0.125f;
            *(float4*)(dst + 4 * c) = t;
        }
    }

    float m[4], lsum[4], o[4][4];
#pragma unroll
    for (int i = 0; i < 4; i++) {
        m[i] = -FLT_MAX; lsum[i] = 0.f;
#pragma unroll
        for (int j = 0; j < 4; j++) o[i][j] = 0.f;
    }

    float4 kreg[4], vreg[4];
    {
        const float* ksrc = qkv + (rowbase + lr) * QKVD_ + DIM_ + hd * HD_ + lcl;
        const float* vsrc = qkv + (rowbase + lr) * QKVD_ + 2 * DIM_ + hd * HD_ + lcl;
#pragma unroll
        for (int c = 0; c < 4; c++) {
            kreg[c] = *(const float4*)(ksrc + 4 * c);
            vreg[c] = *(const float4*)(vsrc + 4 * c);
        }
    }

    for (int t = 0; t < N_ / 64; t++) {
        __syncthreads();
        {
            float* kd = &Ks[lr * ATTN_PAD + lcl];
            float* vd = &Vs[lr * ATTN_PAD + lcl];
#pragma unroll
            for (int c = 0; c < 4; c++) {
                *(float4*)(kd + 4 * c) = kreg[c];
                *(float4*)(vd + 4 * c) = vreg[c];
            }
        }
        __syncthreads();
        if (t + 1 < N_ / 64) {
            const size_t r = rowbase + (size_t)(t + 1) * 64 + lr;
            const float* ksrc = qkv + r * QKVD_ + DIM_ + hd * HD_ + lcl;
            const float* vsrc = qkv + r * QKVD_ + 2 * DIM_ + hd * HD_ + lcl;
#pragma unroll
            for (int c = 0; c < 4; c++) {
                kreg[c] = *(const float4*)(ksrc + 4 * c);
                vreg[c] = *(const float4*)(vsrc + 4 * c);
            }
        }

        float s[4][4];
#pragma unroll
        for (int i = 0; i < 4; i++)
#pragma unroll
            for (int j = 0; j < 4; j++) s[i][j] = 0.f;

#pragma unroll
        for (int d4 = 0; d4 < 16; d4++) {
            float4 qa[4], kb[4];
#pragma unroll
            for (int i = 0; i < 4; i++)
                qa[i] = *(const float4*)&Qs[(ty + 16 * i) * ATTN_PAD + 4 * d4];
#pragma unroll
            for (int j = 0; j < 4; j++)
                kb[j] = *(const float4*)&Ks[(tx + 16 * j) * ATTN_PAD + 4 * d4];
#pragma unroll
            for (int i = 0; i < 4; i++)
#pragma unroll
                for (int j = 0; j < 4; j++)
                    s[i][j] += qa[i].x * kb[j].x + qa[i].y * kb[j].y
                             + qa[i].z * kb[j].z + qa[i].w * kb[j].w;
        }

#pragma unroll
        for (int i = 0; i < 4; i++) {
            float mx = fmaxf(fmaxf(s[i][0], s[i][1]), fmaxf(s[i][2], s[i][3]));
#pragma unroll
            for (int off = 8; off >= 1; off >>= 1)
                mx = fmaxf(mx, __shfl_xor_sync(0xffffffffu, mx, off));
            const float mn = fmaxf(m[i], mx);
            const float p0 = __expf(s[i][0] - mn);
            const float p1 = __expf(s[i][1] - mn);
            const float p2 = __expf(s[i][2] - mn);
            const float p3 = __expf(s[i][3] - mn);
            float ls = p0 + p1 + p2 + p3;
#pragma unroll
            for (int off = 8; off >= 1; off >>= 1)
                ls += __shfl_xor_sync(0xffffffffu, ls, off);
            const float alpha = __expf(m[i] - mn);
            m[i] = mn;
            lsum[i] = lsum[i] * alpha + ls;
            o[i][0] *= alpha; o[i][1] *= alpha; o[i][2] *= alpha; o[i][3] *= alpha;
            float* pr = &Ps[(ty + 16 * i) * ATTN_PAD + tx];
            pr[0] = p0; pr[16] = p1; pr[32] = p2; pr[48] = p3;
        }
        __syncthreads();

#pragma unroll
        for (int k4 = 0; k4 < 16; k4++) {
            float pr[4][4];
#pragma unroll
            for (int i = 0; i < 4; i++) {
                float4 tt = *(const float4*)&Ps[(ty + 16 * i) * ATTN_PAD + 4 * k4];
                pr[i][0] = tt.x; pr[i][1] = tt.y; pr[i][2] = tt.z; pr[i][3] = tt.w;
            }
#pragma unroll
            for (int kk = 0; kk < 4; kk++) {
                float vb[4];
#pragma unroll
                for (int j = 0; j < 4; j++)
                    vb[j] = Vs[(4 * k4 + kk) * ATTN_PAD + tx + 16 * j];
#pragma unroll
                for (int i = 0; i < 4; i++)
#pragma unroll
                    for (int j = 0; j < 4; j++)
                        o[i][j] += pr[i][kk] * vb[j];
            }
        }
    }

#pragma unroll
    for (int i = 0; i < 4; i++) {
        const float invl = 1.f / lsum[i];
        const size_t base = (rowbase + q0 + ty + 16 * i) * DIM_ + hd * HD_ + tx;
#pragma unroll
        for (int j = 0; j < 4; j++) {
            const float v = o[i][j] * invl;
            __nv_bfloat16 hh, ll;
            bf16_split(v, hh, ll);
            outh[base + 16 * j] = hh;
            outl[base + 16 * j] = ll;
        }
    }
}

// ---------------------------------------------------------------------------
// Launch
// ---------------------------------------------------------------------------
extern "C" void kernel_launch(void* const* d_in, const int* in_sizes, int n_in,
                              void* d_out, int out_size)
{
    const float* x      = (const float*)d_in[0];
    const float* ln1_g  = (const float*)d_in[1];
    const float* ln1_b  = (const float*)d_in[2];
    const float* qkv_w  = (const float*)d_in[3];
    const float* qkv_b  = (const float*)d_in[4];
    const float* proj_w = (const float*)d_in[5];
    const float* proj_b = (const float*)d_in[6];
    const float* ln2_g  = (const float*)d_in[7];
    const float* ln2_b  = (const float*)d_in[8];
    const float* fc1_w  = (const float*)d_in[9];
    const float* fc1_b  = (const float*)d_in[10];
    const float* fc2_w  = (const float*)d_in[11];
    const float* fc2_b  = (const float*)d_in[12];
    float* out = (float*)d_out;

    __nv_bfloat16 *phh, *phl, *path, *patl, *ph2h, *ph2l, *pfh, *pfl;
    __nv_bfloat16 *pwqh, *pwql, *pwph, *pwpl, *pw1h, *pw1l, *pw2h, *pw2l;
    float *pqkv, *px1;
    cudaGetSymbolAddress((void**)&phh,  g_hh);
    cudaGetSymbolAddress((void**)&phl,  g_hl);
    cudaGetSymbolAddress((void**)&pqkv, g_qkv);
    cudaGetSymbolAddress((void**)&path, g_ath);
    cudaGetSymbolAddress((void**)&patl, g_atl);
    cudaGetSymbolAddress((void**)&px1,  g_x1);
    cudaGetSymbolAddress((void**)&ph2h, g_h2h);
    cudaGetSymbolAddress((void**)&ph2l, g_h2l);
    cudaGetSymbolAddress((void**)&pfh,  g_fh);
    cudaGetSymbolAddress((void**)&pfl,  g_fl);
    cudaGetSymbolAddress((void**)&pwqh, g_wqh);
    cudaGetSymbolAddress((void**)&pwql, g_wql);
    cudaGetSymbolAddress((void**)&pwph, g_wph);
    cudaGetSymbolAddress((void**)&pwpl, g_wpl);
    cudaGetSymbolAddress((void**)&pw1h, g_w1h);
    cudaGetSymbolAddress((void**)&pw1l, g_w1l);
    cudaGetSymbolAddress((void**)&pw2h, g_w2h);
    cudaGetSymbolAddress((void**)&pw2l, g_w2l);

    cudaFuncSetAttribute(attn_kernel,
                         cudaFuncAttributeMaxDynamicSharedMemorySize, ATTN_SMEM);

    // 0. split weights to (hi, lo) bf16
    split_kernel<<<256, 256>>>(qkv_w,  pwqh, pwql, QKVD_ * DIM_);
    split_kernel<<<256, 256>>>(proj_w, pwph, pwpl, DIM_ * DIM_);
    split_kernel<<<256, 256>>>(fc1_w,  pw1h, pw1l, HID_ * DIM_);
    split_kernel<<<256, 256>>>(fc2_w,  pw2h, pw2l, DIM_ * HID_);

    // 1. h = LN1(x)  -> bf16 split
    ln_kernel<<<TOK, 256>>>(x, ln1_g, ln1_b, phh, phl);
    // 2. qkv = h @ Wqkv^T + b   (fp32 out)
    gemm_mma<0><<<dim3(QKVD_ / 128, TOK / 128), 256>>>(
        phh, phl, pwqh, pwql, qkv_b, nullptr, pqkv, nullptr, nullptr, QKVD_, DIM_);
    // 3. attention -> bf16 split
    attn_kernel<<<dim3(N_ / 64, B_ * NH_), 256, ATTN_SMEM>>>(pqkv, path, patl);
    // 4. x1 = x + attn @ Wproj^T + b
    gemm_mma<1><<<dim3(DIM_ / 128, TOK / 128), 256>>>(
        path, patl, pwph, pwpl, proj_b, x, px1, nullptr, nullptr, DIM_, DIM_);
    // 5. h2 = LN2(x1) -> bf16 split
    ln_kernel<<<TOK, 256>>>(px1, ln2_g, ln2_b, ph2h, ph2l);
    // 6. ffn = gelu(h2 @ Wfc1^T + b) -> bf16 split
    gemm_mma<2><<<dim3(HID_ / 128, TOK / 128), 256>>>(
        ph2h, ph2l, pw1h, pw1l, fc1_b, nullptr, nullptr, pfh, pfl, HID_, DIM_);
    // 7. out = x1 + ffn @ Wfc2^T + b
    gemm_mma<1><<<dim3(DIM_ / 128, TOK / 128), 256>>>(
        pfh, pfl, pw2h, pw2l, fc2_b, px1, out, nullptr, nullptr, DIM_, HID_);
}